// round 16
// baseline (speedup 1.0000x reference)
#include <cuda_runtime.h>

#define NU     10
#define TIN    50
#define TOUT   3
#define NTHR   128
#define ELEMS  256     // elements per block: 2 per thread, one f32x2 pair
#define TCH    10      // time-steps per smem staging chunk
#define ROWW   258     // 256 + 2 pad

typedef unsigned long long u64;

// ===== f32x2 packed primitives =====
__device__ __forceinline__ u64 fma2(u64 a, u64 b, u64 c) {
    u64 d;
    asm("fma.rn.f32x2 %0, %1, %2, %3;" : "=l"(d) : "l"(a), "l"(b), "l"(c));
    return d;
}
__device__ __forceinline__ u64 mul2(u64 a, u64 b) {
    u64 d;
    asm("mul.rn.f32x2 %0, %1, %2;" : "=l"(d) : "l"(a), "l"(b));
    return d;
}
__device__ __forceinline__ u64 mk2(float lo, float hi) {
    u64 r;
    asm("mov.b64 %0, {%1, %2};" : "=l"(r)
        : "r"(__float_as_uint(lo)), "r"(__float_as_uint(hi)));
    return r;
}
__device__ __forceinline__ float2 un2(u64 v) {
    unsigned lo, hi;
    asm("mov.b64 {%0, %1}, %2;" : "=r"(lo), "=r"(hi) : "l"(v));
    return make_float2(__uint_as_float(lo), __uint_as_float(hi));
}
__device__ __forceinline__ u64 splat(float w) { return mk2(w, w); }

__device__ __forceinline__ u64 rlu2(u64 a) {
    float2 f = un2(a);
    return mk2(fmaxf(f.x, 0.0f), fmaxf(f.y, 0.0f));
}
__device__ __forceinline__ float tanhap(float x) {
    float t;
    asm("tanh.approx.f32 %0, %1;" : "=f"(t) : "f"(x));
    return t;
}
__device__ __forceinline__ u64 sgm2(u64 a, u64 h2) {
    // sigmoid via 0.5*tanh(0.5x)+0.5 (packed scale/offset, 2 MUFU)
    const float2 f = un2(mul2(a, h2));
    return fma2(mk2(tanhap(f.x), tanhap(f.y)), h2, h2);
}
__device__ __forceinline__ u64 bits2(float w) {
    u64 b = (u64)__float_as_uint(w);
    return (b << 32) | b;
}

// 10-element dot, scalar weight row (12 floats, 16B aligned):
// 3x LDS.128 + 10 splats + 10 fma2.
__device__ __forceinline__ u64 dotrow(const float* __restrict__ r,
                                      const u64* h, u64 z) {
    const float4 a = reinterpret_cast<const float4*>(r)[0];
    const float4 b = reinterpret_cast<const float4*>(r)[1];
    const float4 c = reinterpret_cast<const float4*>(r)[2];  // [8],[9],pad,pad
    z = fma2(h[0], splat(a.x), z);
    z = fma2(h[1], splat(a.y), z);
    z = fma2(h[2], splat(a.z), z);
    z = fma2(h[3], splat(a.w), z);
    z = fma2(h[4], splat(b.x), z);
    z = fma2(h[5], splat(b.y), z);
    z = fma2(h[6], splat(b.z), z);
    z = fma2(h[7], splat(b.w), z);
    z = fma2(h[8], splat(c.x), z);
    z = fma2(h[9], splat(c.y), z);
    return z;
}

__global__ __launch_bounds__(NTHR, 6)   // 85-reg cap => 6 blocks (24 warps)/SM
void seq2seq_relu_lstm(const float* __restrict__ inputs,
                       const float* __restrict__ W1,
                       const float* __restrict__ R1,
                       const float* __restrict__ b1,
                       const float* __restrict__ W2,
                       const float* __restrict__ R2,
                       const float* __restrict__ b2,
                       const float* __restrict__ Wd,
                       const float* __restrict__ bd,
                       float* __restrict__ out,
                       long long B) {
    __shared__ __align__(16) float xs[TCH * ROWW];      // staged input chunk
    __shared__ __align__(16) float r1w[40][12];         // gate-major scalar rows
    __shared__ __align__(16) float w2w[40][12];
    __shared__ __align__(16) float r2w[40][12];
    __shared__ __align__(16) u64 w1p[40];               // dup-packed W1
    __shared__ __align__(16) u64 b1p[40];               // dup-packed b1
    __shared__ __align__(16) u64 b2p[40];               // dup-packed b2
    __shared__ __align__(16) u64 wdp[10];               // dup-packed Wd

    const int tid = threadIdx.x;

    // stage gate-major scalar weight rows
    for (int k = tid; k < 480; k += NTHR) {
        const int g = k / 12, j = k % 12;
        if (j < 10) {
            r1w[g][j] = R1[j * 40 + g];
            w2w[g][j] = W2[j * 40 + g];
            r2w[g][j] = R2[j * 40 + g];
        } else {
            r1w[g][j] = 0.0f;
            w2w[g][j] = 0.0f;
            r2w[g][j] = 0.0f;
        }
    }
    // stage dup-packed vectors
    for (int g = tid; g < 40; g += NTHR) {
        w1p[g] = bits2(W1[g]);
        b1p[g] = bits2(b1[g]);
        b2p[g] = bits2(b2[g]);
    }
    for (int u = tid; u < 10; u += NTHR) wdp[u] = bits2(Wd[u]);

    const long long base = (long long)blockIdx.x * ELEMS;
    const u64 h2 = splat(0.5f);

    // ======== LSTM1: 5 staged chunks of 10 steps ========
    u64 h[NU], c[NU];
#pragma unroll
    for (int u = 0; u < NU; u++) { h[u] = 0ull; c[u] = 0ull; }

#pragma unroll 1
    for (int ch = 0; ch < TIN / TCH; ch++) {
        __syncthreads();
#pragma unroll 1
        for (int k = tid; k < ELEMS * TCH; k += NTHR) {
            const int e = k / TCH, tq = k % TCH;
            long long eg = base + e;
            if (eg >= B) eg = B - 1;
            xs[tq * ROWW + e] = inputs[eg * TIN + ch * TCH + tq];
        }
        __syncthreads();

#pragma unroll 1
        for (int tq = 0; tq < TCH; tq++) {
            const float* xr = xs + tq * ROWW;
            const u64 x2 = mk2(xr[tid], xr[128 + tid]);
            u64 hn[NU];
#pragma unroll 1
            for (int u = 0; u < NU; u++) {
                u64 zi = dotrow(r1w[u],      h, fma2(x2, w1p[u],      b1p[u]));
                u64 zf = dotrow(r1w[10 + u], h, fma2(x2, w1p[10 + u], b1p[10 + u]));
                u64 zg = dotrow(r1w[20 + u], h, fma2(x2, w1p[20 + u], b1p[20 + u]));
                u64 zo = dotrow(r1w[30 + u], h, fma2(x2, w1p[30 + u], b1p[30 + u]));
                const u64 gi = sgm2(zi, h2);
                const u64 gf = sgm2(zf, h2);
                const u64 gg = rlu2(zg);
                const u64 go = sgm2(zo, h2);
                c[u] = fma2(gf, c[u], mul2(gi, gg));
                hn[u] = mul2(go, rlu2(c[u]));
            }
#pragma unroll
            for (int u = 0; u < NU; u++) h[u] = hn[u];
        }
    }

    // ======== LSTM2, RepeatVector fused (input == h1 every step) ========
    u64 h1[NU];
#pragma unroll
    for (int u = 0; u < NU; u++) { h1[u] = h[u]; h[u] = 0ull; c[u] = 0ull; }

    const u64 bdp = splat(bd[0]);
    const long long e0 = base + tid;

#pragma unroll 1
    for (int s = 0; s < TOUT; s++) {
        u64 hn[NU];
#pragma unroll 1
        for (int u = 0; u < NU; u++) {
            u64 zi = dotrow(r2w[u],      h, dotrow(w2w[u],      h1, b2p[u]));
            u64 zf = dotrow(r2w[10 + u], h, dotrow(w2w[10 + u], h1, b2p[10 + u]));
            u64 zg = dotrow(r2w[20 + u], h, dotrow(w2w[20 + u], h1, b2p[20 + u]));
            u64 zo = dotrow(r2w[30 + u], h, dotrow(w2w[30 + u], h1, b2p[30 + u]));
            const u64 gi = sgm2(zi, h2);
            const u64 gf = sgm2(zf, h2);
            const u64 gg = rlu2(zg);
            const u64 go = sgm2(zo, h2);
            c[u] = fma2(gf, c[u], mul2(gi, gg));
            hn[u] = mul2(go, rlu2(c[u]));
        }
        u64 acc = bdp;
#pragma unroll
        for (int u = 0; u < NU; u++) {
            h[u] = hn[u];
            acc = fma2(hn[u], wdp[u], acc);
        }
        const float2 o = un2(acc);
        if (e0 < B)       out[e0 * TOUT + s] = o.x;
        if (e0 + 128 < B) out[(e0 + 128) * TOUT + s] = o.y;
    }
}

extern "C" void kernel_launch(void* const* d_in, const int* in_sizes, int n_in,
                              void* d_out, int out_size) {
    const float* inputs = (const float*)d_in[0];
    const float* W1 = (const float*)d_in[1];
    const float* R1 = (const float*)d_in[2];
    const float* b1 = (const float*)d_in[3];
    const float* W2 = (const float*)d_in[4];
    const float* R2 = (const float*)d_in[5];
    const float* b2 = (const float*)d_in[6];
    const float* Wd = (const float*)d_in[7];
    const float* bd = (const float*)d_in[8];
    float* out = (float*)d_out;

    const long long B = in_sizes[0] / TIN;
    const int nblk = (int)((B + ELEMS - 1) / ELEMS);
    seq2seq_relu_lstm<<<nblk, NTHR>>>(inputs, W1, R1, b1, W2, R2, b2,
                                      Wd, bd, out, B);
}

// round 17
// speedup vs baseline: 1.1437x; 1.1437x over previous
#include <cuda_runtime.h>

#define UNITS  10
#define T_IN   50
#define T_OUT  3
#define TPB    128
#define EPB    256     // elements per block = 2 per thread (1 packed pair)
#define TCHUNK 10      // time-steps staged per smem chunk
#define XROW   258     // 256 elems + 2 pad

typedef unsigned long long u64;

// ---------- packed f32x2 helpers ----------
__device__ __forceinline__ u64 pack2(float lo, float hi) {
    u64 r;
    asm("mov.b64 %0, {%1, %2};" : "=l"(r)
        : "r"(__float_as_uint(lo)), "r"(__float_as_uint(hi)));
    return r;
}
__device__ __forceinline__ float2 unpack2(u64 v) {
    unsigned lo, hi;
    asm("mov.b64 {%0, %1}, %2;" : "=r"(lo), "=r"(hi) : "l"(v));
    return make_float2(__uint_as_float(lo), __uint_as_float(hi));
}
__device__ __forceinline__ u64 fma2(u64 a, u64 b, u64 c) {
    u64 d;
    asm("fma.rn.f32x2 %0, %1, %2, %3;" : "=l"(d) : "l"(a), "l"(b), "l"(c));
    return d;
}
__device__ __forceinline__ u64 mul2(u64 a, u64 b) {
    u64 d;
    asm("mul.rn.f32x2 %0, %1, %2;" : "=l"(d) : "l"(a), "l"(b));
    return d;
}
__device__ __forceinline__ u64 relu2(u64 a) {
    float2 f = unpack2(a);
    return pack2(fmaxf(f.x, 0.0f), fmaxf(f.y, 0.0f));
}
__device__ __forceinline__ float tanh_ap(float x) {
    float t;
    asm("tanh.approx.f32 %0, %1;" : "=f"(t) : "f"(x));
    return t;
}
// packed sigmoid: 0.5*tanh(0.5x)+0.5 — packed mul/fma, 2 MUFU
__device__ __forceinline__ u64 sig2(u64 a, u64 half2) {
    const float2 f = unpack2(mul2(a, half2));
    return fma2(pack2(tanh_ap(f.x), tanh_ap(f.y)), half2, half2);
}
// splat a scalar float into both f32x2 lanes (ALU mov)
__device__ __forceinline__ u64 dup2(float w) {
    return pack2(w, w);
}

// pair 10-dot over a SCALAR weight row (12 floats, 16B aligned):
// 3x LDS.128, 10 splat movs, 10 fma2.
__device__ __forceinline__ u64 dot10p(const float* __restrict__ row,
                                      const u64* h, u64 z) {
    const float4 wa = reinterpret_cast<const float4*>(row)[0];
    const float4 wb = reinterpret_cast<const float4*>(row)[1];
    const float4 wc = reinterpret_cast<const float4*>(row)[2];  // w8,w9,pad,pad
    z = fma2(h[0], dup2(wa.x), z);
    z = fma2(h[1], dup2(wa.y), z);
    z = fma2(h[2], dup2(wa.z), z);
    z = fma2(h[3], dup2(wa.w), z);
    z = fma2(h[4], dup2(wb.x), z);
    z = fma2(h[5], dup2(wb.y), z);
    z = fma2(h[6], dup2(wb.z), z);
    z = fma2(h[7], dup2(wb.w), z);
    z = fma2(h[8], dup2(wc.x), z);
    z = fma2(h[9], dup2(wc.y), z);
    return z;
}

__global__ __launch_bounds__(TPB, 5)   // 102-reg cap; 5 blocks = 20 warps/SM
void lstm_seq2seq_kernel(const float* __restrict__ inputs,
                         const float* __restrict__ W1,
                         const float* __restrict__ R1,
                         const float* __restrict__ b1,
                         const float* __restrict__ W2,
                         const float* __restrict__ R2,
                         const float* __restrict__ b2,
                         const float* __restrict__ Wd,
                         const float* __restrict__ bd,
                         float* __restrict__ out,
                         long long B) {
    __shared__ __align__(16) float sX[TCHUNK * XROW];   // ~10.3 KB input chunk
    __shared__ __align__(16) float sR1[40][12];         // gate-major SCALAR rows
    __shared__ __align__(16) float sW2[40][12];
    __shared__ __align__(16) float sR2[40][12];
    __shared__ __align__(16) float2 sWB1[40];           // {W1[g], b1[g]}
    __shared__ __align__(16) float sB2[40];
    __shared__ __align__(16) float sWd[10];

    const int tid = threadIdx.x;

    // ---- stage scalar weights, gate-major (transpose) ----
    for (int idx = tid; idx < 480; idx += TPB) {        // 40 x 12
        int g = idx / 12, j = idx % 12;
        const bool v = (j < 10);
        sR1[g][j] = v ? R1[j * 40 + g] : 0.0f;
        sW2[g][j] = v ? W2[j * 40 + g] : 0.0f;
        sR2[g][j] = v ? R2[j * 40 + g] : 0.0f;
    }
    if (tid < 40) {
        sWB1[tid] = make_float2(W1[tid], b1[tid]);
        sB2[tid] = b2[tid];
    }
    if (tid < 10) sWd[tid] = Wd[tid];

    const long long blockBase = (long long)blockIdx.x * EPB;
    const u64 half2 = dup2(0.5f);

    // ---------------- LSTM1 over 5 x 10-step chunks ----------------
    u64 h[UNITS], c[UNITS];
#pragma unroll
    for (int u = 0; u < UNITS; u++) { h[u] = 0ull; c[u] = 0ull; }

#pragma unroll 1
    for (int ch = 0; ch < T_IN / TCHUNK; ch++) {
        __syncthreads();   // weights visible (ch=0) / prev chunk consumed
#pragma unroll 1
        for (int idx = tid; idx < EPB * TCHUNK; idx += TPB) {
            int e = idx / TCHUNK, tq = idx % TCHUNK;
            long long eg = blockBase + e;
            if (eg >= B) eg = B - 1;
            sX[tq * XROW + e] = inputs[eg * T_IN + ch * TCHUNK + tq];
        }
        __syncthreads();

#pragma unroll 1
        for (int tq = 0; tq < TCHUNK; tq++) {
            const float* xr = sX + tq * XROW;
            const u64 x2 = pack2(xr[tid], xr[128 + tid]);
            u64 hn[UNITS];
            // unroll 2: overlap next unit's weight LDS under current FMAs
#pragma unroll 2
            for (int u = 0; u < UNITS; u++) {
                const float2 fI = sWB1[u];
                const float2 fF = sWB1[10 + u];
                const float2 fG = sWB1[20 + u];
                const float2 fO = sWB1[30 + u];
                u64 zi = dot10p(sR1[u],      h, fma2(x2, dup2(fI.x), dup2(fI.y)));
                u64 zf = dot10p(sR1[10 + u], h, fma2(x2, dup2(fF.x), dup2(fF.y)));
                u64 zg = dot10p(sR1[20 + u], h, fma2(x2, dup2(fG.x), dup2(fG.y)));
                u64 zo = dot10p(sR1[30 + u], h, fma2(x2, dup2(fO.x), dup2(fO.y)));
                const u64 gi = sig2(zi, half2);
                const u64 gf = sig2(zf, half2);
                const u64 gg = relu2(zg);
                const u64 go = sig2(zo, half2);
                c[u] = fma2(gf, c[u], mul2(gi, gg));
                hn[u] = mul2(go, relu2(c[u]));
            }
#pragma unroll
            for (int u = 0; u < UNITS; u++) h[u] = hn[u];
        }
    }

    // ---------------- LSTM2 (RepeatVector fused) ----------------
    u64 h1[UNITS];
#pragma unroll
    for (int u = 0; u < UNITS; u++) { h1[u] = h[u]; h[u] = 0ull; c[u] = 0ull; }

    const u64 bd2 = dup2(bd[0]);
    const long long e0 = blockBase + tid;

#pragma unroll 1
    for (int s = 0; s < T_OUT; s++) {
        u64 hn[UNITS];
#pragma unroll 2
        for (int u = 0; u < UNITS; u++) {
            u64 zi = dot10p(sR2[u],      h, dot10p(sW2[u],      h1, dup2(sB2[u])));
            u64 zf = dot10p(sR2[10 + u], h, dot10p(sW2[10 + u], h1, dup2(sB2[10 + u])));
            u64 zg = dot10p(sR2[20 + u], h, dot10p(sW2[20 + u], h1, dup2(sB2[20 + u])));
            u64 zo = dot10p(sR2[30 + u], h, dot10p(sW2[30 + u], h1, dup2(sB2[30 + u])));
            const u64 gi = sig2(zi, half2);
            const u64 gf = sig2(zf, half2);
            const u64 gg = relu2(zg);
            const u64 go = sig2(zo, half2);
            c[u] = fma2(gf, c[u], mul2(gi, gg));
            hn[u] = mul2(go, relu2(c[u]));
        }
        u64 acc = bd2;
#pragma unroll
        for (int u = 0; u < UNITS; u++) {
            h[u] = hn[u];
            acc = fma2(hn[u], dup2(sWd[u]), acc);
        }
        const float2 o = unpack2(acc);
        if (e0 < B)       out[e0 * T_OUT + s] = o.x;
        if (e0 + 128 < B) out[(e0 + 128) * T_OUT + s] = o.y;
    }
}

extern "C" void kernel_launch(void* const* d_in, const int* in_sizes, int n_in,
                              void* d_out, int out_size) {
    const float* inputs = (const float*)d_in[0];
    const float* W1 = (const float*)d_in[1];
    const float* R1 = (const float*)d_in[2];
    const float* b1 = (const float*)d_in[3];
    const float* W2 = (const float*)d_in[4];
    const float* R2 = (const float*)d_in[5];
    const float* b2 = (const float*)d_in[6];
    const float* Wd = (const float*)d_in[7];
    const float* bd = (const float*)d_in[8];
    float* out = (float*)d_out;

    const long long B = in_sizes[0] / T_IN;
    const int blocks = (int)((B + EPB - 1) / EPB);
    lstm_seq2seq_kernel<<<blocks, TPB>>>(inputs, W1, R1, b1, W2, R2, b2,
                                         Wd, bd, out, B);
}